// round 3
// baseline (speedup 1.0000x reference)
#include <cuda_runtime.h>
#include <cuda_bf16.h>
#include <stdint.h>

#define NN 100000
#define EE 1600000
#define FIN 128
#define HH 32
#define CC 16
#define GG 64
#define FULLM 0xffffffffu

// ---------------- static device scratch (no allocs allowed) ----------------
__device__ unsigned char g_vidx[NN];
__device__ int   g_deg[NN];
__device__ int   g_wr[NN];
__device__ int   g_rowptr[NN + 1];
__device__ int   g_bsums[128];
__device__ unsigned int g_csr[EE];
__device__ float g_embW1[128 * HH];
__device__ float g_stab[128];
__device__ float g_dtab[128];
__device__ float g_h2lin[NN * CC];
__device__ float g_a2s[NN];
__device__ float g_a2d[NN];
__device__ float g_pool[GG * CC];
__device__ float g_cnt[GG];

// ---------------- init ----------------
__global__ void k_zero() {
    int i = blockIdx.x * 256 + threadIdx.x;
    if (i < NN) { g_deg[i] = 0; g_wr[i] = 0; }
    if (i < GG * CC) g_pool[i] = 0.f;
    if (i < GG) g_cnt[i] = 0.f;
}

// vocab tables: embW1 = emb @ W1 (128x32), s_tab = embW1 @ a1_src, d_tab = embW1 @ a1_dst
__global__ void k_tables(const float* __restrict__ emb, const float* __restrict__ W1,
                         const float* __restrict__ a1s, const float* __restrict__ a1d) {
    __shared__ float sW1[HH * HH];
    __shared__ float sas[HH], sad[HH];
    int t = threadIdx.x; // 128 threads
    for (int i = t; i < HH * HH; i += 128) sW1[i] = W1[i];
    if (t < HH) { sas[t] = a1s[t]; sad[t] = a1d[t]; }
    __syncthreads();
    float e[HH];
#pragma unroll
    for (int j = 0; j < HH; j++) e[j] = emb[t * HH + j];
    float ss = 0.f, dd = 0.f;
#pragma unroll 4
    for (int k = 0; k < HH; k++) {
        float sum = 0.f;
#pragma unroll
        for (int j = 0; j < HH; j++) sum += e[j] * sW1[j * HH + k];
        g_embW1[t * HH + k] = sum;
        ss += sum * sas[k];
        dd += sum * sad[k];
    }
    g_stab[t] = ss;
    g_dtab[t] = dd;
}

// argmax over 128 features, warp per node
__global__ void k_argmax(const float* __restrict__ x) {
    int i = blockIdx.x * 8 + (threadIdx.x >> 5);
    if (i >= NN) return;
    int lane = threadIdx.x & 31;
    const float4* row = (const float4*)(x + (size_t)i * FIN);
    float4 v = row[lane];
    float bv = v.x; int bi = lane * 4;
    if (v.y > bv) { bv = v.y; bi = lane * 4 + 1; }
    if (v.z > bv) { bv = v.z; bi = lane * 4 + 2; }
    if (v.w > bv) { bv = v.w; bi = lane * 4 + 3; }
#pragma unroll
    for (int off = 16; off; off >>= 1) {
        float ov = __shfl_xor_sync(FULLM, bv, off);
        int   oi = __shfl_xor_sync(FULLM, bi, off);
        if (ov > bv || (ov == bv && oi < bi)) { bv = ov; bi = oi; }
    }
    if (!lane) g_vidx[i] = (unsigned char)bi;
}

// degree count (real edges only; self loops handled analytically)
__global__ void k_count(const int* __restrict__ ei) {
    int e = blockIdx.x * 256 + threadIdx.x;
    if (e < EE) atomicAdd(&g_deg[ei[EE + e]], 1);
}

// ----- 3-kernel exclusive scan of g_deg -> g_rowptr -----
__global__ void k_breduce() {
    __shared__ int sh[1024];
    int i = blockIdx.x * 1024 + threadIdx.x;
    sh[threadIdx.x] = (i < NN) ? g_deg[i] : 0;
    __syncthreads();
    for (int s = 512; s > 0; s >>= 1) {
        if (threadIdx.x < s) sh[threadIdx.x] += sh[threadIdx.x + s];
        __syncthreads();
    }
    if (!threadIdx.x) g_bsums[blockIdx.x] = sh[0];
}

__global__ void k_bscan(int nb) {
    __shared__ int sh[128];
    int t = threadIdx.x;
    int v = (t < nb) ? g_bsums[t] : 0;
    sh[t] = v;
    __syncthreads();
    for (int off = 1; off < 128; off <<= 1) {
        int add = (t >= off) ? sh[t - off] : 0;
        __syncthreads();
        if (t >= off) sh[t] += add;
        __syncthreads();
    }
    g_bsums[t] = (t ? sh[t - 1] : 0);
}

__global__ void k_scanblocks() {
    __shared__ int sh[1024];
    int t = threadIdx.x;
    int gi = blockIdx.x * 1024 + t;
    int v = (gi < NN) ? g_deg[gi] : 0;
    sh[t] = v;
    __syncthreads();
    for (int off = 1; off < 1024; off <<= 1) {
        int add = (t >= off) ? sh[t - off] : 0;
        __syncthreads();
        if (t >= off) sh[t] += add;
        __syncthreads();
    }
    int incl = sh[t];
    int base = g_bsums[blockIdx.x];
    if (gi < NN) g_rowptr[gi] = incl - v + base;
    if (gi == NN - 1) g_rowptr[NN] = incl + base;
}

// scatter edges into CSR by dst; pack (vidx[src] << 24) | src
__global__ void k_scatter(const int* __restrict__ ei) {
    int e = blockIdx.x * 256 + threadIdx.x;
    if (e >= EE) return;
    int s = ei[e];
    int d = ei[EE + e];
    int pos = g_rowptr[d] + atomicAdd(&g_wr[d], 1);
    g_csr[pos] = ((unsigned)g_vidx[s] << 24) | (unsigned)s;
}

// ----- layer 1 aggregation (warp per dst node) + fused layer-2 linear/attention prep -----
__global__ void k_layer1(const float* __restrict__ b1, const float* __restrict__ W2,
                         const float* __restrict__ a2src, const float* __restrict__ a2dst) {
    __shared__ float s_s[128], s_d[128];
    __shared__ float s_e[128 * HH];     // embW1 rows (conflict-free: lanes read consecutive words)
    __shared__ float s_b1[HH];
    __shared__ float s_W2[HH * CC];
    __shared__ float s_a2s[CC], s_a2d[CC];
    __shared__ float s_h1[8][HH];

    int tid = threadIdx.x;
    if (tid < 128) { s_s[tid] = g_stab[tid]; s_d[tid] = g_dtab[tid]; }
    for (int i = tid; i < 128 * HH; i += 256) s_e[i] = g_embW1[i];
    if (tid < HH) s_b1[tid] = b1[tid];
    for (int i = tid; i < HH * CC; i += 256) s_W2[i] = W2[i];
    if (tid < CC) { s_a2s[tid] = a2src[tid]; s_a2d[tid] = a2dst[tid]; }
    __syncthreads();

    int w = tid >> 5;
    int i = blockIdx.x * 8 + w;
    if (i >= NN) return;
    int lane = tid & 31;

    int vi = g_vidx[i];
    float ad = s_d[vi];
    float es = s_s[vi] + ad;
    es = es > 0.f ? es : 0.2f * es;

    int start = g_rowptr[i], end = g_rowptr[i + 1];

    // pass 1: max
    float m = es;
    for (int j = start + lane; j < end; j += 32) {
        unsigned p = g_csr[j];
        float e = s_s[p >> 24] + ad;
        e = e > 0.f ? e : 0.2f * e;
        m = fmaxf(m, e);
    }
#pragma unroll
    for (int off = 16; off; off >>= 1) m = fmaxf(m, __shfl_xor_sync(FULLM, m, off));

    // pass 2: exp-sum + weighted accumulate (lane owns dim k=lane)
    float exs = __expf(es - m);
    float acc = exs * s_e[vi * HH + lane];
    float dloc = 0.f;
    for (int base = start; base < end; base += 32) {
        int j = base + lane;
        unsigned p = 0; float ex = 0.f;
        if (j < end) {
            p = g_csr[j];
            float e = s_s[p >> 24] + ad;
            e = e > 0.f ? e : 0.2f * e;
            ex = __expf(e - m);
            dloc += ex;
        }
        int cnt = min(32, end - base);
        for (int t = 0; t < cnt; t++) {
            float    exb = __shfl_sync(FULLM, ex, t);
            unsigned pb  = __shfl_sync(FULLM, p, t);
            acc += exb * s_e[(pb >> 24) * HH + lane];
        }
    }
    float den = dloc;
#pragma unroll
    for (int off = 16; off; off >>= 1) den += __shfl_xor_sync(FULLM, den, off);
    den += exs;

    float h1 = acc / (den + 1e-16f) + s_b1[lane];
    h1 = fmaxf(h1, 0.f);

    s_h1[w][lane] = h1;
    __syncwarp();

    // layer-2 linear: h2lin = h1 @ W2  (lanes 0..15 own output channels)
    float hv = 0.f;
    if (lane < CC) {
        float sum = 0.f;
#pragma unroll
        for (int k = 0; k < HH; k++) sum += s_h1[w][k] * s_W2[k * CC + lane];
        hv = sum;
        g_h2lin[i * CC + lane] = sum;
    }
    float ps = (lane < CC) ? hv * s_a2s[lane] : 0.f;
    float pd = (lane < CC) ? hv * s_a2d[lane] : 0.f;
#pragma unroll
    for (int off = 16; off; off >>= 1) {
        ps += __shfl_xor_sync(FULLM, ps, off);
        pd += __shfl_xor_sync(FULLM, pd, off);
    }
    if (!lane) { g_a2s[i] = ps; g_a2d[i] = pd; }
}

// ----- layer 2 aggregation (warp per dst node) + fused mean-pool accumulation -----
__global__ void k_layer2(const int* __restrict__ batch, const float* __restrict__ b2) {
    __shared__ float s_b2[CC];
    if (threadIdx.x < CC) s_b2[threadIdx.x] = b2[threadIdx.x];
    __syncthreads();

    int i = blockIdx.x * 8 + (threadIdx.x >> 5);
    if (i >= NN) return;
    int lane = threadIdx.x & 31;

    float ad = g_a2d[i];
    float es = g_a2s[i] + ad;
    es = es > 0.f ? es : 0.2f * es;

    int start = g_rowptr[i], end = g_rowptr[i + 1];

    float m = es;
    for (int j = start + lane; j < end; j += 32) {
        unsigned p = g_csr[j];
        float e = g_a2s[p & 0xFFFFFFu] + ad;
        e = e > 0.f ? e : 0.2f * e;
        m = fmaxf(m, e);
    }
#pragma unroll
    for (int off = 16; off; off >>= 1) m = fmaxf(m, __shfl_xor_sync(FULLM, m, off));

    float exs = __expf(es - m);
    float acc = (lane < CC) ? exs * g_h2lin[i * CC + lane] : 0.f;
    float dloc = 0.f;
    for (int base = start; base < end; base += 32) {
        int j = base + lane;
        unsigned p = 0; float ex = 0.f;
        if (j < end) {
            p = g_csr[j];
            float e = g_a2s[p & 0xFFFFFFu] + ad;
            e = e > 0.f ? e : 0.2f * e;
            ex = __expf(e - m);
            dloc += ex;
        }
        int cnt = min(32, end - base);
        for (int t = 0; t < cnt; t++) {
            float    exb = __shfl_sync(FULLM, ex, t);
            unsigned pb  = __shfl_sync(FULLM, p, t);
            if (lane < CC) acc += exb * g_h2lin[(pb & 0xFFFFFFu) * CC + lane];
        }
    }
    float den = dloc;
#pragma unroll
    for (int off = 16; off; off >>= 1) den += __shfl_xor_sync(FULLM, den, off);
    den += exs;

    if (lane < CC) {
        float h2 = acc / (den + 1e-16f) + s_b2[lane];
        int g = batch[i];
        atomicAdd(&g_pool[g * CC + lane], h2);
        if (!lane) atomicAdd(&g_cnt[g], 1.0f);
    }
}

// ----- final: mean + softmax over [G, C] -----
__global__ void k_final(float* __restrict__ out) {
    int g = threadIdx.x;
    if (g >= GG) return;
    float c = fmaxf(g_cnt[g], 1.0f);
    float v[CC];
    float mx = -1e30f;
#pragma unroll
    for (int j = 0; j < CC; j++) { v[j] = g_pool[g * CC + j] / c; mx = fmaxf(mx, v[j]); }
    float s = 0.f;
#pragma unroll
    for (int j = 0; j < CC; j++) { v[j] = __expf(v[j] - mx); s += v[j]; }
    float inv = 1.0f / s;
#pragma unroll
    for (int j = 0; j < CC; j++) out[g * CC + j] = v[j] * inv;
}

// ---------------- launch ----------------
extern "C" void kernel_launch(void* const* d_in, const int* in_sizes, int n_in,
                              void* d_out, int out_size) {
    const float* x      = (const float*)d_in[0];
    const int*   ei     = (const int*)d_in[1];
    const int*   batch  = (const int*)d_in[2];
    const float* emb    = (const float*)d_in[3];
    const float* W1     = (const float*)d_in[4];
    const float* a1s    = (const float*)d_in[5];
    const float* a1d    = (const float*)d_in[6];
    const float* b1     = (const float*)d_in[7];
    const float* W2     = (const float*)d_in[8];
    const float* a2s    = (const float*)d_in[9];
    const float* a2d    = (const float*)d_in[10];
    const float* b2     = (const float*)d_in[11];
    float* out = (float*)d_out;

    const int nodeBlocks = (NN + 7) / 8;            // 12500 (warp per node, 8 warps/block)
    const int edgeBlocks = (EE + 255) / 256;        // 6250
    const int scanBlocks = (NN + 1023) / 1024;      // 98

    k_zero<<<(NN + 255) / 256, 256>>>();
    k_tables<<<1, 128>>>(emb, W1, a1s, a1d);
    k_argmax<<<nodeBlocks, 256>>>(x);
    k_count<<<edgeBlocks, 256>>>(ei);
    k_breduce<<<scanBlocks, 1024>>>();
    k_bscan<<<1, 128>>>(scanBlocks);
    k_scanblocks<<<scanBlocks, 1024>>>();
    k_scatter<<<edgeBlocks, 256>>>(ei);
    k_layer1<<<nodeBlocks, 256>>>(b1, W2, a2s, a2d);
    k_layer2<<<nodeBlocks, 256>>>(batch, b2);
    k_final<<<1, 64>>>(out);
    (void)in_sizes; (void)n_in; (void)out_size;
}

// round 4
// speedup vs baseline: 1.0467x; 1.0467x over previous
#include <cuda_runtime.h>
#include <cuda_bf16.h>
#include <stdint.h>

#define NN 100000
#define EE 1600000
#define FIN 128
#define HH 32
#define CC 16
#define GG 64
#define FULLM 0xffffffffu
#define SRCMASK 0xFFFFFFu

// ---------------- static device scratch (no allocs allowed) ----------------
__device__ unsigned char g_vidx[NN];
__device__ int   g_deg[NN];
__device__ int   g_rowptr[NN + 1];
__device__ int   g_bsums[128];
__device__ int   g_ticket[EE];
__device__ unsigned int g_csr[EE];
__device__ float g_embW1[128 * HH];
__device__ float g_stab[128];
__device__ float g_dtab[128];
__device__ float g_h2lin[NN * CC];
__device__ float g_a2s[NN];
__device__ float g_a2d[NN];
__device__ float g_pool[GG * CC];
__device__ float g_cnt[GG];

// ---------------- init ----------------
__global__ void k_zero() {
    int i = blockIdx.x * 256 + threadIdx.x;
    if (i < NN) g_deg[i] = 0;
    if (i < GG * CC) g_pool[i] = 0.f;
    if (i < GG) g_cnt[i] = 0.f;
}

// vocab tables: embW1 = emb @ W1 (128x32), s_tab = embW1 @ a1_src, d_tab = embW1 @ a1_dst
__global__ void k_tables(const float* __restrict__ emb, const float* __restrict__ W1,
                         const float* __restrict__ a1s, const float* __restrict__ a1d) {
    __shared__ float sW1[HH * HH];
    __shared__ float sas[HH], sad[HH];
    int t = threadIdx.x; // 128 threads
    for (int i = t; i < HH * HH; i += 128) sW1[i] = W1[i];
    if (t < HH) { sas[t] = a1s[t]; sad[t] = a1d[t]; }
    __syncthreads();
    float e[HH];
#pragma unroll
    for (int j = 0; j < HH; j++) e[j] = emb[t * HH + j];
    float ss = 0.f, dd = 0.f;
#pragma unroll 4
    for (int k = 0; k < HH; k++) {
        float sum = 0.f;
#pragma unroll
        for (int j = 0; j < HH; j++) sum += e[j] * sW1[j * HH + k];
        g_embW1[t * HH + k] = sum;
        ss += sum * sas[k];
        dd += sum * sad[k];
    }
    g_stab[t] = ss;
    g_dtab[t] = dd;
}

// argmax over 128 features, warp per node
__global__ void k_argmax(const float* __restrict__ x) {
    int i = blockIdx.x * 8 + (threadIdx.x >> 5);
    if (i >= NN) return;
    int lane = threadIdx.x & 31;
    const float4* row = (const float4*)(x + (size_t)i * FIN);
    float4 v = row[lane];
    float bv = v.x; int bi = lane * 4;
    if (v.y > bv) { bv = v.y; bi = lane * 4 + 1; }
    if (v.z > bv) { bv = v.z; bi = lane * 4 + 2; }
    if (v.w > bv) { bv = v.w; bi = lane * 4 + 3; }
#pragma unroll
    for (int off = 16; off; off >>= 1) {
        float ov = __shfl_xor_sync(FULLM, bv, off);
        int   oi = __shfl_xor_sync(FULLM, bi, off);
        if (ov > bv || (ov == bv && oi < bi)) { bv = ov; bi = oi; }
    }
    if (!lane) g_vidx[i] = (unsigned char)bi;
}

// degree count + ticket (4 edges per thread, int4 loads)
__global__ void k_count(const int* __restrict__ ei) {
    int e4 = blockIdx.x * 256 + threadIdx.x;   // EE/4 work items
    if (e4 * 4 >= EE) return;
    int4 d = ((const int4*)(ei + EE))[e4];
    int4 t;
    t.x = atomicAdd(&g_deg[d.x], 1);
    t.y = atomicAdd(&g_deg[d.y], 1);
    t.z = atomicAdd(&g_deg[d.z], 1);
    t.w = atomicAdd(&g_deg[d.w], 1);
    ((int4*)g_ticket)[e4] = t;
}

// ----- 3-kernel exclusive scan of g_deg -> g_rowptr -----
__global__ void k_breduce() {
    __shared__ int sh[1024];
    int i = blockIdx.x * 1024 + threadIdx.x;
    sh[threadIdx.x] = (i < NN) ? g_deg[i] : 0;
    __syncthreads();
    for (int s = 512; s > 0; s >>= 1) {
        if (threadIdx.x < s) sh[threadIdx.x] += sh[threadIdx.x + s];
        __syncthreads();
    }
    if (!threadIdx.x) g_bsums[blockIdx.x] = sh[0];
}

__global__ void k_bscan(int nb) {
    __shared__ int sh[128];
    int t = threadIdx.x;
    int v = (t < nb) ? g_bsums[t] : 0;
    sh[t] = v;
    __syncthreads();
    for (int off = 1; off < 128; off <<= 1) {
        int add = (t >= off) ? sh[t - off] : 0;
        __syncthreads();
        if (t >= off) sh[t] += add;
        __syncthreads();
    }
    g_bsums[t] = (t ? sh[t - 1] : 0);
}

__global__ void k_scanblocks() {
    __shared__ int sh[1024];
    int t = threadIdx.x;
    int gi = blockIdx.x * 1024 + t;
    int v = (gi < NN) ? g_deg[gi] : 0;
    sh[t] = v;
    __syncthreads();
    for (int off = 1; off < 1024; off <<= 1) {
        int add = (t >= off) ? sh[t - off] : 0;
        __syncthreads();
        if (t >= off) sh[t] += add;
        __syncthreads();
    }
    int incl = sh[t];
    int base = g_bsums[blockIdx.x];
    if (gi < NN) g_rowptr[gi] = incl - v + base;
    if (gi == NN - 1) g_rowptr[NN] = incl + base;
}

// atomic-free scatter using tickets; pack (vidx[src] << 24) | src
__global__ void k_scatter(const int* __restrict__ ei) {
    int e4 = blockIdx.x * 256 + threadIdx.x;
    if (e4 * 4 >= EE) return;
    int4 s = ((const int4*)ei)[e4];
    int4 d = ((const int4*)(ei + EE))[e4];
    int4 t = ((const int4*)g_ticket)[e4];
    g_csr[g_rowptr[d.x] + t.x] = ((unsigned)g_vidx[s.x] << 24) | (unsigned)s.x;
    g_csr[g_rowptr[d.y] + t.y] = ((unsigned)g_vidx[s.y] << 24) | (unsigned)s.y;
    g_csr[g_rowptr[d.z] + t.z] = ((unsigned)g_vidx[s.z] << 24) | (unsigned)s.z;
    g_csr[g_rowptr[d.w] + t.w] = ((unsigned)g_vidx[s.w] << 24) | (unsigned)s.w;
}

// ----- layer 1: single-pass softmax (m=0), warp per dst node, fused layer-2 linear -----
__global__ void k_layer1(const float* __restrict__ b1, const float* __restrict__ W2,
                         const float* __restrict__ a2src, const float* __restrict__ a2dst) {
    __shared__ float s_s[128], s_d[128];
    __shared__ float s_e[128 * HH];     // embW1 rows (broadcast-row reads: conflict-free)
    __shared__ float s_b1[HH];
    __shared__ float s_W2[HH * CC];
    __shared__ float s_a2s[CC], s_a2d[CC];
    __shared__ float s_h1[8][HH];

    int tid = threadIdx.x;
    if (tid < 128) { s_s[tid] = g_stab[tid]; s_d[tid] = g_dtab[tid]; }
    for (int i = tid; i < 128 * HH; i += 256) s_e[i] = g_embW1[i];
    if (tid < HH) s_b1[tid] = b1[tid];
    for (int i = tid; i < HH * CC; i += 256) s_W2[i] = W2[i];
    if (tid < CC) { s_a2s[tid] = a2src[tid]; s_a2d[tid] = a2dst[tid]; }
    __syncthreads();

    int w = tid >> 5;
    int i = blockIdx.x * 8 + w;
    if (i >= NN) return;
    int lane = tid & 31;

    int vi = g_vidx[i];
    float ad = s_d[vi];
    float es = s_s[vi] + ad;
    es = es > 0.f ? es : 0.2f * es;
    float exs = __expf(es);                      // self-loop term (m = 0)

    int start = g_rowptr[i], end = g_rowptr[i + 1];

    float acc = exs * s_e[vi * HH + lane];
    float dloc = 0.f;
    for (int base = start; base < end; base += 32) {
        int j = base + lane;
        unsigned p = 0; float ex = 0.f;
        if (j < end) {
            p = g_csr[j];
            float e = s_s[p >> 24] + ad;
            e = e > 0.f ? e : 0.2f * e;
            ex = __expf(e);
            dloc += ex;
        }
        int cnt = min(32, end - base);
        for (int t = 0; t < cnt; t++) {
            float    exb = __shfl_sync(FULLM, ex, t);
            unsigned pb  = __shfl_sync(FULLM, p, t);
            acc += exb * s_e[(pb >> 24) * HH + lane];
        }
    }
    float den = dloc;
#pragma unroll
    for (int off = 16; off; off >>= 1) den += __shfl_xor_sync(FULLM, den, off);
    den += exs;

    float h1 = acc / (den + 1e-16f) + s_b1[lane];
    h1 = fmaxf(h1, 0.f);

    s_h1[w][lane] = h1;
    __syncwarp();

    // layer-2 linear: h2lin = h1 @ W2  (lanes 0..15 own output channels)
    float hv = 0.f;
    if (lane < CC) {
        float sum = 0.f;
#pragma unroll
        for (int k = 0; k < HH; k++) sum += s_h1[w][k] * s_W2[k * CC + lane];
        hv = sum;
        g_h2lin[i * CC + lane] = sum;
    }
    float ps = (lane < CC) ? hv * s_a2s[lane] : 0.f;
    float pd = (lane < CC) ? hv * s_a2d[lane] : 0.f;
#pragma unroll
    for (int off = 16; off; off >>= 1) {
        ps += __shfl_xor_sync(FULLM, ps, off);
        pd += __shfl_xor_sync(FULLM, pd, off);
    }
    if (!lane) { g_a2s[i] = ps; g_a2d[i] = pd; }
}

// ----- layer 2: single-pass softmax (m=0), warp per dst, half-warp edge pairing,
//       fused mean-pool accumulation -----
__global__ void k_layer2(const int* __restrict__ batch, const float* __restrict__ b2) {
    __shared__ float s_b2[CC];
    if (threadIdx.x < CC) s_b2[threadIdx.x] = b2[threadIdx.x];
    __syncthreads();

    int i = blockIdx.x * 8 + (threadIdx.x >> 5);
    if (i >= NN) return;
    int lane = threadIdx.x & 31;
    int half = lane >> 4;        // 0: edge t, 1: edge t+1
    int c    = lane & 15;        // channel

    float ad = g_a2d[i];
    float es = g_a2s[i] + ad;
    es = es > 0.f ? es : 0.2f * es;
    float exs = __expf(es);

    int start = g_rowptr[i], end = g_rowptr[i + 1];

    float acc = (half == 0) ? exs * g_h2lin[i * CC + c] : 0.f;   // self-loop once
    float dloc = 0.f;
    for (int base = start; base < end; base += 32) {
        int j = base + lane;
        unsigned p = 0; float ex = 0.f;
        if (j < end) {
            p = g_csr[j];
            float e = g_a2s[p & SRCMASK] + ad;
            e = e > 0.f ? e : 0.2f * e;
            ex = __expf(e);
            dloc += ex;
        }
        int cnt = min(32, end - base);
        for (int t = 0; t < cnt; t += 2) {
            int tt = t + half;                       // may equal cnt (odd): ex there is 0
            float    exb = __shfl_sync(FULLM, ex, tt);
            unsigned pb  = __shfl_sync(FULLM, p, tt);
            acc += exb * g_h2lin[(pb & SRCMASK) * CC + c];   // exb==0 kills invalid
        }
    }
    float den = dloc;
#pragma unroll
    for (int off = 16; off; off >>= 1) den += __shfl_xor_sync(FULLM, den, off);
    den += exs;

    acc += __shfl_xor_sync(FULLM, acc, 16);          // fold the two halves

    if (lane < CC) {
        float h2 = acc / (den + 1e-16f) + s_b2[lane];
        int g = batch[i];
        atomicAdd(&g_pool[g * CC + lane], h2);
        if (!lane) atomicAdd(&g_cnt[g], 1.0f);
    }
}

// ----- final: mean + softmax over [G, C] -----
__global__ void k_final(float* __restrict__ out) {
    int g = threadIdx.x;
    if (g >= GG) return;
    float cden = fmaxf(g_cnt[g], 1.0f);
    float v[CC];
    float mx = -1e30f;
#pragma unroll
    for (int j = 0; j < CC; j++) { v[j] = g_pool[g * CC + j] / cden; mx = fmaxf(mx, v[j]); }
    float s = 0.f;
#pragma unroll
    for (int j = 0; j < CC; j++) { v[j] = __expf(v[j] - mx); s += v[j]; }
    float inv = 1.0f / s;
#pragma unroll
    for (int j = 0; j < CC; j++) out[g * CC + j] = v[j] * inv;
}

// ---------------- launch ----------------
extern "C" void kernel_launch(void* const* d_in, const int* in_sizes, int n_in,
                              void* d_out, int out_size) {
    const float* x      = (const float*)d_in[0];
    const int*   ei     = (const int*)d_in[1];
    const int*   batch  = (const int*)d_in[2];
    const float* emb    = (const float*)d_in[3];
    const float* W1     = (const float*)d_in[4];
    const float* a1s    = (const float*)d_in[5];
    const float* a1d    = (const float*)d_in[6];
    const float* b1     = (const float*)d_in[7];
    const float* W2     = (const float*)d_in[8];
    const float* a2s    = (const float*)d_in[9];
    const float* a2d    = (const float*)d_in[10];
    const float* b2     = (const float*)d_in[11];
    float* out = (float*)d_out;

    const int nodeBlocks  = (NN + 7) / 8;             // warp per node, 8 warps/block
    const int edge4Blocks = (EE / 4 + 255) / 256;     // 4 edges per thread
    const int scanBlocks  = (NN + 1023) / 1024;       // 98

    k_zero<<<(NN + 255) / 256, 256>>>();
    k_tables<<<1, 128>>>(emb, W1, a1s, a1d);
    k_argmax<<<nodeBlocks, 256>>>(x);
    k_count<<<edge4Blocks, 256>>>(ei);
    k_breduce<<<scanBlocks, 1024>>>();
    k_bscan<<<1, 128>>>(scanBlocks);
    k_scanblocks<<<scanBlocks, 1024>>>();
    k_scatter<<<edge4Blocks, 256>>>(ei);
    k_layer1<<<nodeBlocks, 256>>>(b1, W2, a2s, a2d);
    k_layer2<<<nodeBlocks, 256>>>(batch, b2);
    k_final<<<1, 64>>>(out);
    (void)in_sizes; (void)n_in; (void)out_size;
}

// round 5
// speedup vs baseline: 1.7834x; 1.7039x over previous
#include <cuda_runtime.h>
#include <cuda_bf16.h>
#include <stdint.h>

#define NN 100000
#define EE 1600000
#define FIN 128
#define HH 32
#define CC 16
#define GG 64
#define FULLM 0xffffffffu
#define SRCMASK 0xFFFFFFu
#define NODEB 12500   // blocks for argmax (8 warps/node each)
#define EDGEB 6250    // blocks for count (256 edges each)

// ---------------- static device scratch ----------------
__device__ unsigned char g_vidx[NN];
__device__ int   g_deg[NN];
__device__ int   g_rowptr[NN + 1];
__device__ int   g_bsums[128];
__device__ int   g_ticket[EE];
__device__ unsigned int g_csr[EE];
__device__ float g_embW1[128 * HH];
__device__ float g_stab[128];
__device__ float g_dtab[128];
__device__ float g_h2lin[NN * CC];
__device__ float g_h2out[NN * CC];
__device__ float g_a2s[NN];
__device__ float g_a2d[NN];

// ---------------- init ----------------
__global__ void k_zero() {
    int i = blockIdx.x * 256 + threadIdx.x;
    if (i < NN) g_deg[i] = 0;
}

// vocab tables: embW1 = emb @ W1 (128x32), stab = embW1 @ a1_src, dtab = embW1 @ a1_dst
__global__ void k_tables(const float* __restrict__ emb, const float* __restrict__ W1,
                         const float* __restrict__ a1s, const float* __restrict__ a1d) {
    __shared__ float sW1[HH * HH];
    __shared__ float sas[HH], sad[HH];
    int t = threadIdx.x; // 128 threads
    for (int i = t; i < HH * HH; i += 128) sW1[i] = W1[i];
    if (t < HH) { sas[t] = a1s[t]; sad[t] = a1d[t]; }
    __syncthreads();
    float e[HH];
#pragma unroll
    for (int j = 0; j < HH; j++) e[j] = emb[t * HH + j];
    float ss = 0.f, dd = 0.f;
#pragma unroll 4
    for (int k = 0; k < HH; k++) {
        float sum = 0.f;
#pragma unroll
        for (int j = 0; j < HH; j++) sum += e[j] * sW1[j * HH + k];
        g_embW1[t * HH + k] = sum;
        ss += sum * sas[k];
        dd += sum * sad[k];
    }
    g_stab[t] = ss;
    g_dtab[t] = dd;
}

// merged: argmax (blocks [0,NODEB)) + degree count with tickets (blocks [NODEB,NODEB+EDGEB))
__global__ void k_argmax_count(const float* __restrict__ x, const int* __restrict__ ei) {
    if (blockIdx.x < NODEB) {
        int i = blockIdx.x * 8 + (threadIdx.x >> 5);
        if (i >= NN) return;
        int lane = threadIdx.x & 31;
        const float4* row = (const float4*)(x + (size_t)i * FIN);
        float4 v = row[lane];
        float bv = v.x; int bi = lane * 4;
        if (v.y > bv) { bv = v.y; bi = lane * 4 + 1; }
        if (v.z > bv) { bv = v.z; bi = lane * 4 + 2; }
        if (v.w > bv) { bv = v.w; bi = lane * 4 + 3; }
#pragma unroll
        for (int off = 16; off; off >>= 1) {
            float ov = __shfl_xor_sync(FULLM, bv, off);
            int   oi = __shfl_xor_sync(FULLM, bi, off);
            if (ov > bv || (ov == bv && oi < bi)) { bv = ov; bi = oi; }
        }
        if (!lane) g_vidx[i] = (unsigned char)bi;
    } else {
        int e = (blockIdx.x - NODEB) * 256 + threadIdx.x;
        if (e < EE) {
            int d = ei[EE + e];
            g_ticket[e] = atomicAdd(&g_deg[d], 1);
        }
    }
}

// ----- 3-kernel exclusive scan of g_deg -> g_rowptr -----
__global__ void k_breduce() {
    __shared__ int sh[1024];
    int i = blockIdx.x * 1024 + threadIdx.x;
    sh[threadIdx.x] = (i < NN) ? g_deg[i] : 0;
    __syncthreads();
    for (int s = 512; s > 0; s >>= 1) {
        if (threadIdx.x < s) sh[threadIdx.x] += sh[threadIdx.x + s];
        __syncthreads();
    }
    if (!threadIdx.x) g_bsums[blockIdx.x] = sh[0];
}

__global__ void k_bscan(int nb) {
    __shared__ int sh[128];
    int t = threadIdx.x;
    int v = (t < nb) ? g_bsums[t] : 0;
    sh[t] = v;
    __syncthreads();
    for (int off = 1; off < 128; off <<= 1) {
        int add = (t >= off) ? sh[t - off] : 0;
        __syncthreads();
        if (t >= off) sh[t] += add;
        __syncthreads();
    }
    g_bsums[t] = (t ? sh[t - 1] : 0);
}

__global__ void k_scanblocks() {
    __shared__ int sh[1024];
    int t = threadIdx.x;
    int gi = blockIdx.x * 1024 + t;
    int v = (gi < NN) ? g_deg[gi] : 0;
    sh[t] = v;
    __syncthreads();
    for (int off = 1; off < 1024; off <<= 1) {
        int add = (t >= off) ? sh[t - off] : 0;
        __syncthreads();
        if (t >= off) sh[t] += add;
        __syncthreads();
    }
    int incl = sh[t];
    int base = g_bsums[blockIdx.x];
    if (gi < NN) g_rowptr[gi] = incl - v + base;
    if (gi == NN - 1) g_rowptr[NN] = incl + base;
}

// atomic-free scatter using tickets; pack (vidx[src] << 24) | src
__global__ void k_scatter(const int* __restrict__ ei) {
    int e4 = blockIdx.x * 256 + threadIdx.x;
    if (e4 * 4 >= EE) return;
    int4 s = ((const int4*)ei)[e4];
    int4 d = ((const int4*)(ei + EE))[e4];
    int4 t = ((const int4*)g_ticket)[e4];
    g_csr[g_rowptr[d.x] + t.x] = ((unsigned)g_vidx[s.x] << 24) | (unsigned)s.x;
    g_csr[g_rowptr[d.y] + t.y] = ((unsigned)g_vidx[s.y] << 24) | (unsigned)s.y;
    g_csr[g_rowptr[d.z] + t.z] = ((unsigned)g_vidx[s.z] << 24) | (unsigned)s.z;
    g_csr[g_rowptr[d.w] + t.w] = ((unsigned)g_vidx[s.w] << 24) | (unsigned)s.w;
}

// ----- layer 1: warp per dst node, 4 edges per broadcast step (8 lanes/edge, float4),
//       table reads via __ldg (16KB, L1-resident), fused layer-2 linear -----
__global__ __launch_bounds__(512) void k_layer1(
        const float* __restrict__ b1, const float* __restrict__ W2,
        const float* __restrict__ a2src, const float* __restrict__ a2dst) {
    __shared__ float s_s[128], s_d[128];
    __shared__ float s_b1[HH];
    __shared__ float s_W2[HH * CC];
    __shared__ float s_a2s[CC], s_a2d[CC];
    __shared__ float s_h1[16][HH];

    int tid = threadIdx.x;
    if (tid < 128) { s_s[tid] = g_stab[tid]; s_d[tid] = g_dtab[tid]; }
    s_W2[tid] = W2[tid];                       // 512 == HH*CC
    if (tid < HH) s_b1[tid] = b1[tid];
    if (tid < CC) { s_a2s[tid] = a2src[tid]; s_a2d[tid] = a2dst[tid]; }
    __syncthreads();

    int w = tid >> 5;
    int i = blockIdx.x * 16 + w;
    if (i >= NN) return;
    int lane = tid & 31;
    int sub  = lane & 7;   // float4 chunk of the 32-dim row
    int quad = lane >> 3;  // edge slot within a broadcast step

    const float4* etab = (const float4*)g_embW1;

    int vi = g_vidx[i];
    float ad = s_d[vi];
    float es = s_s[vi] + ad;
    es = es > 0.f ? es : 0.2f * es;
    float exs = __expf(es);                      // self-loop term (m = 0)

    float4 acc = make_float4(0.f, 0.f, 0.f, 0.f);
    if (quad == 0) {
        float4 r = __ldg(&etab[vi * 8 + sub]);
        acc.x = exs * r.x; acc.y = exs * r.y; acc.z = exs * r.z; acc.w = exs * r.w;
    }

    int start = g_rowptr[i], end = g_rowptr[i + 1];
    float dloc = 0.f;
    for (int base = start; base < end; base += 32) {
        int j = base + lane;
        unsigned p = 0; float ex = 0.f;
        if (j < end) {
            p = g_csr[j];
            float e = s_s[p >> 24] + ad;
            e = e > 0.f ? e : 0.2f * e;
            ex = __expf(e);
            dloc += ex;
        }
        int cnt = min(32, end - base);
        int steps = (cnt + 3) >> 2;
        for (int s = 0; s < steps; s++) {
            int t = (s << 2) + quad;                 // <= 31
            float    exb = __shfl_sync(FULLM, ex, t);
            unsigned pb  = __shfl_sync(FULLM, p, t);
            float4 r = __ldg(&etab[(pb >> 24) * 8 + sub]);
            acc.x += exb * r.x; acc.y += exb * r.y;
            acc.z += exb * r.z; acc.w += exb * r.w;
        }
    }
    float den = dloc;
#pragma unroll
    for (int off = 16; off; off >>= 1) den += __shfl_xor_sync(FULLM, den, off);
    den += exs;

    // fold the 4 edge-slots
#pragma unroll
    for (int off = 8; off <= 16; off <<= 1) {
        acc.x += __shfl_xor_sync(FULLM, acc.x, off);
        acc.y += __shfl_xor_sync(FULLM, acc.y, off);
        acc.z += __shfl_xor_sync(FULLM, acc.z, off);
        acc.w += __shfl_xor_sync(FULLM, acc.w, off);
    }

    float inv = 1.0f / (den + 1e-16f);
    if (quad == 0) {
        float4 h;
        h.x = fmaxf(acc.x * inv + s_b1[sub * 4 + 0], 0.f);
        h.y = fmaxf(acc.y * inv + s_b1[sub * 4 + 1], 0.f);
        h.z = fmaxf(acc.z * inv + s_b1[sub * 4 + 2], 0.f);
        h.w = fmaxf(acc.w * inv + s_b1[sub * 4 + 3], 0.f);
        ((float4*)s_h1[w])[sub] = h;
    }
    __syncwarp();

    // layer-2 linear: h2lin = h1 @ W2  (lanes 0..15 own output channels)
    float ps = 0.f, pd = 0.f;
    if (lane < CC) {
        float sum = 0.f;
#pragma unroll
        for (int k = 0; k < HH; k++) sum += s_h1[w][k] * s_W2[k * CC + lane];
        g_h2lin[i * CC + lane] = sum;
        ps = sum * s_a2s[lane];
        pd = sum * s_a2d[lane];
    }
#pragma unroll
    for (int off = 16; off; off >>= 1) {
        ps += __shfl_xor_sync(FULLM, ps, off);
        pd += __shfl_xor_sync(FULLM, pd, off);
    }
    if (!lane) { g_a2s[i] = ps; g_a2d[i] = pd; }
}

// ----- layer 2: warp per dst node, 8 edges per broadcast step (4 lanes/edge, float4),
//       plain store of h2 (pooling moved to k_final) -----
__global__ __launch_bounds__(512) void k_layer2(const float* __restrict__ b2) {
    __shared__ float s_b2[CC];
    if (threadIdx.x < CC) s_b2[threadIdx.x] = b2[threadIdx.x];
    __syncthreads();

    int w = threadIdx.x >> 5;
    int i = blockIdx.x * 16 + w;
    if (i >= NN) return;
    int lane = threadIdx.x & 31;
    int sub = lane & 3;    // float4 chunk of the 16-dim row
    int oct = lane >> 2;   // edge slot (8 per step)

    const float4* hl = (const float4*)g_h2lin;

    float ad = g_a2d[i];
    float es = g_a2s[i] + ad;
    es = es > 0.f ? es : 0.2f * es;
    float exs = __expf(es);

    float4 acc = make_float4(0.f, 0.f, 0.f, 0.f);
    if (oct == 0) {
        float4 r = __ldg(&hl[i * 4 + sub]);
        acc.x = exs * r.x; acc.y = exs * r.y; acc.z = exs * r.z; acc.w = exs * r.w;
    }

    int start = g_rowptr[i], end = g_rowptr[i + 1];
    float dloc = 0.f;
    for (int base = start; base < end; base += 32) {
        int j = base + lane;
        unsigned p = 0; float ex = 0.f;
        if (j < end) {
            p = g_csr[j];
            float e = g_a2s[p & SRCMASK] + ad;
            e = e > 0.f ? e : 0.2f * e;
            ex = __expf(e);
            dloc += ex;
        }
        int cnt = min(32, end - base);
        int steps = (cnt + 7) >> 3;
        for (int s = 0; s < steps; s++) {
            int t = (s << 3) + oct;                  // <= 31
            float    exb = __shfl_sync(FULLM, ex, t);
            unsigned pb  = __shfl_sync(FULLM, p, t);
            float4 r = __ldg(&hl[(pb & SRCMASK) * 4 + sub]);
            acc.x += exb * r.x; acc.y += exb * r.y;
            acc.z += exb * r.z; acc.w += exb * r.w;
        }
    }
    float den = dloc;
#pragma unroll
    for (int off = 16; off; off >>= 1) den += __shfl_xor_sync(FULLM, den, off);
    den += exs;

    // fold the 8 edge-slots
#pragma unroll
    for (int off = 4; off <= 16; off <<= 1) {
        acc.x += __shfl_xor_sync(FULLM, acc.x, off);
        acc.y += __shfl_xor_sync(FULLM, acc.y, off);
        acc.z += __shfl_xor_sync(FULLM, acc.z, off);
        acc.w += __shfl_xor_sync(FULLM, acc.w, off);
    }

    float inv = 1.0f / (den + 1e-16f);
    if (oct == 0) {
        float4 h;
        h.x = acc.x * inv + s_b2[sub * 4 + 0];
        h.y = acc.y * inv + s_b2[sub * 4 + 1];
        h.z = acc.z * inv + s_b2[sub * 4 + 2];
        h.w = acc.w * inv + s_b2[sub * 4 + 3];
        ((float4*)g_h2out)[i * 4 + sub] = h;
    }
}

// ----- final: segmented mean-pool (batch sorted) + softmax; block per graph -----
__device__ __forceinline__ int lbound(const int* a, int n, int v) {
    int lo = 0, hi = n;
    while (lo < hi) { int m = (lo + hi) >> 1; if (a[m] < v) lo = m + 1; else hi = m; }
    return lo;
}

__global__ void k_final(const int* __restrict__ batch, float* __restrict__ out) {
    __shared__ int s_lo, s_hi;
    __shared__ float4 s_acc[256];
    int g = blockIdx.x;
    if (threadIdx.x == 0) s_lo = lbound(batch, NN, g);
    if (threadIdx.x == 1) s_hi = lbound(batch, NN, g + 1);
    __syncthreads();
    int lo = s_lo, hi = s_hi;

    int nodelane = threadIdx.x >> 2;
    int sub = threadIdx.x & 3;
    float4 acc = make_float4(0.f, 0.f, 0.f, 0.f);
    const float4* ho = (const float4*)g_h2out;
    for (int n = lo + nodelane; n < hi; n += 64) {
        float4 v = ho[n * 4 + sub];
        acc.x += v.x; acc.y += v.y; acc.z += v.z; acc.w += v.w;
    }
    s_acc[threadIdx.x] = acc;
    __syncthreads();
    for (int off = 128; off >= 4; off >>= 1) {
        if (threadIdx.x < off) {
            float4 a = s_acc[threadIdx.x], b = s_acc[threadIdx.x + off];
            a.x += b.x; a.y += b.y; a.z += b.z; a.w += b.w;
            s_acc[threadIdx.x] = a;
        }
        __syncthreads();
    }
    if (threadIdx.x == 0) {
        float cden = fmaxf((float)(hi - lo), 1.0f);
        float v[CC];
        float mx = -1e30f;
#pragma unroll
        for (int s = 0; s < 4; s++) {
            float4 a = s_acc[s];
            v[s * 4 + 0] = a.x / cden; v[s * 4 + 1] = a.y / cden;
            v[s * 4 + 2] = a.z / cden; v[s * 4 + 3] = a.w / cden;
        }
#pragma unroll
        for (int j = 0; j < CC; j++) mx = fmaxf(mx, v[j]);
        float ssum = 0.f;
#pragma unroll
        for (int j = 0; j < CC; j++) { v[j] = __expf(v[j] - mx); ssum += v[j]; }
        float inv = 1.0f / ssum;
#pragma unroll
        for (int j = 0; j < CC; j++) out[g * CC + j] = v[j] * inv;
    }
}

// ---------------- launch ----------------
extern "C" void kernel_launch(void* const* d_in, const int* in_sizes, int n_in,
                              void* d_out, int out_size) {
    const float* x      = (const float*)d_in[0];
    const int*   ei     = (const int*)d_in[1];
    const int*   batch  = (const int*)d_in[2];
    const float* emb    = (const float*)d_in[3];
    const float* W1     = (const float*)d_in[4];
    const float* a1s    = (const float*)d_in[5];
    const float* a1d    = (const float*)d_in[6];
    const float* b1     = (const float*)d_in[7];
    const float* W2     = (const float*)d_in[8];
    const float* a2s    = (const float*)d_in[9];
    const float* a2d    = (const float*)d_in[10];
    const float* b2     = (const float*)d_in[11];
    float* out = (float*)d_out;

    const int node16Blocks = (NN + 15) / 16;          // 6250 (16 warps/block)
    const int edge4Blocks  = (EE / 4 + 255) / 256;    // 1563
    const int scanBlocks   = (NN + 1023) / 1024;      // 98

    k_zero<<<(NN + 255) / 256, 256>>>();
    k_tables<<<1, 128>>>(emb, W1, a1s, a1d);
    k_argmax_count<<<NODEB + EDGEB, 256>>>(x, ei);
    k_breduce<<<scanBlocks, 1024>>>();
    k_bscan<<<1, 128>>>(scanBlocks);
    k_scanblocks<<<scanBlocks, 1024>>>();
    k_scatter<<<edge4Blocks, 256>>>(ei);
    k_layer1<<<node16Blocks, 512>>>(b1, W2, a2s, a2d);
    k_layer2<<<node16Blocks, 512>>>(b2);
    k_final<<<GG, 256>>>(batch, out);
    (void)in_sizes; (void)n_in; (void)out_size;
}